// round 8
// baseline (speedup 1.0000x reference)
#include <cuda_runtime.h>
#include <cuda_bf16.h>
#include <cstdint>
#include <math.h>

// Problem constants
#define T_LEN 2048
#define D_DIM 4096
#define NHEAD 32
#define NGRP 8
#define HDIM 128
#define KVDIM 2048   // 2 * HDIM * NGRP

// Scratch (no cudaMalloc allowed)
__device__ float    g_q[T_LEN * D_DIM];        // 32 MB
__device__ float    g_kv[T_LEN * KVDIM];       // 16 MB
__device__ float    g_ctx[T_LEN * D_DIM];      // 32 MB (tf32-rounded bits)
__device__ uint32_t g_xtf[T_LEN * D_DIM];      // 32 MB  x  tf32 bits [T][D]
__device__ uint32_t g_wq32[D_DIM * D_DIM];     // 64 MB  Wq tf32 bits [K][N]
__device__ uint32_t g_wkv32[D_DIM * KVDIM];    // 32 MB  Wkv tf32 bits [K][N]
__device__ uint32_t g_wo32[D_DIM * D_DIM];     // 64 MB  Wo tf32 bits [K][N]

// ---------------------------------------------------------------------------
// Helpers
// ---------------------------------------------------------------------------
__device__ __forceinline__ uint32_t smem_u32(const void* p) {
    uint32_t a;
    asm("{ .reg .u64 t; cvta.to.shared.u64 t, %1; cvt.u32.u64 %0, t; }"
        : "=r"(a) : "l"(p));
    return a;
}
#define CP_ASYNC16(smem, gptr) \
    asm volatile("cp.async.cg.shared.global [%0], [%1], 16;" \
                 :: "r"(smem), "l"(gptr) : "memory")
#define CP_COMMIT() asm volatile("cp.async.commit_group;" ::: "memory")
#define CP_WAIT(N)  asm volatile("cp.async.wait_group %0;" :: "n"(N) : "memory")

__device__ __forceinline__ uint32_t f2tf32(float f) {
    uint32_t u;
    asm("cvt.rna.tf32.f32 %0, %1;" : "=r"(u) : "f"(f));
    return u;
}
__device__ __forceinline__ void mma_tf32(float* c, const uint32_t* a,
                                         const uint32_t* b) {
    asm volatile(
        "mma.sync.aligned.m16n8k8.row.col.f32.tf32.tf32.f32 "
        "{%0,%1,%2,%3}, {%4,%5,%6,%7}, {%8,%9}, {%0,%1,%2,%3};"
        : "+f"(c[0]), "+f"(c[1]), "+f"(c[2]), "+f"(c[3])
        : "r"(a[0]), "r"(a[1]), "r"(a[2]), "r"(a[3]), "r"(b[0]), "r"(b[1]));
}

// ---------------------------------------------------------------------------
// Prepass: elementwise f32 -> tf32 bits (no layout change)
// ---------------------------------------------------------------------------
__global__ __launch_bounds__(256) void cvt_tf32(
    const float4* __restrict__ in, uint4* __restrict__ out, int n4)
{
    int i = blockIdx.x * 256 + threadIdx.x;
    if (i < n4) {
        float4 v = in[i];
        uint4 o;
        o.x = f2tf32(v.x); o.y = f2tf32(v.y);
        o.z = f2tf32(v.z); o.w = f2tf32(v.w);
        out[i] = o;
    }
}

// ---------------------------------------------------------------------------
// tf32 mma.sync GEMM, multistage.
// C[M,N] = A[M,K] @ B[K,N] (+bias).  A,B pre-converted tf32 bits.
// BM=128, BN=128, BK=32, 256 threads (8 warps 2x4), warp tile 64x32.
// 3 cp.async stages, ONE __syncthreads per stage.
// Stage smem: A[128][36] u32 + B[32][136] u32 = 35840 B; 3 stages = 107520 B.
// ---------------------------------------------------------------------------
#define GK 4096
#define NKT (GK / 32)          // 128 stages of BK=32
#define ASTR 36                // 32 + 4 pad
#define BSTR 136               // 128 + 8 pad (proven)
#define A_U (128 * ASTR)       // 4608
#define B_U (32 * BSTR)        // 4352
#define STAGE_U (A_U + B_U)    // 8960 u32 = 35840 B
#define NSTAGE 3
#define GSMEM_BYTES (NSTAGE * STAGE_U * 4)   // 107520

__global__ __launch_bounds__(256, 2) void gemm_mma(
    const uint32_t* __restrict__ A, const uint32_t* __restrict__ B,
    float* __restrict__ C, const float* __restrict__ bias, int N)
{
    extern __shared__ uint32_t sh[];
    const uint32_t smb = smem_u32(sh);

    const int tid = threadIdx.x;
    const int wid = tid >> 5;
    const int lane = tid & 31;
    const int gid = lane >> 2;
    const int tig = lane & 3;
    const int warp_m = (wid & 1) * 64;
    const int warp_n = (wid >> 1) * 32;

    const int bx = blockIdx.x;
    const int by = blockIdx.y;

    const uint32_t* Ab = A + (size_t)by * 128 * GK;
    const uint32_t* Bb = B + (size_t)bx * 128;

    // Loader slots: A 1024 chunks (128 rows x 8 chunks), 4 per thread;
    //               B 1024 chunks (32 rows x 32 chunks), 4 per thread.
    const int a_r = tid >> 1;              // 0..127
    const int a_k = (tid & 1) * 16;        // 0 or 16 -> covers [a_k, a_k+16)
    const int b_r = tid >> 5;              // 0..7 (+8,+16,+24)
    const int b_c = (tid & 31) * 4;        // 0..124

    auto load_tile = [&](int kt, int s) {
        const uint32_t* ag = Ab + kt * 32;
        const uint32_t* bg = Bb + (size_t)(kt * 32) * N;
        uint32_t sb = smb + 4 * (s * STAGE_U);
        // A: row a_r, k cols [a_k, a_k+16) -> 4 chunks of 16B
        uint32_t aoff = sb + 4 * (a_r * ASTR + a_k);
        const uint32_t* agp = ag + (size_t)a_r * GK + a_k;
        CP_ASYNC16(aoff,      agp);
        CP_ASYNC16(aoff + 16, agp + 4);
        CP_ASYNC16(aoff + 32, agp + 8);
        CP_ASYNC16(aoff + 48, agp + 12);
        // B: rows b_r+8rr, col chunk b_c
        uint32_t boff = sb + 4 * (A_U + b_r * BSTR + b_c);
        const uint32_t* bgp = bg + (size_t)b_r * N + b_c;
#pragma unroll
        for (int rr = 0; rr < 4; rr++)
            CP_ASYNC16(boff + 4 * (8 * rr * BSTR),
                       bgp + (size_t)(8 * rr) * N);
        CP_COMMIT();
    };

    float acc[4][4][4];
#pragma unroll
    for (int i = 0; i < 4; i++)
#pragma unroll
        for (int j = 0; j < 4; j++)
#pragma unroll
            for (int k = 0; k < 4; k++) acc[i][j][k] = 0.f;

    load_tile(0, 0);
    load_tile(1, 1);

    for (int kt = 0; kt < NKT; kt++) {
        if (kt < NKT - 1) { CP_WAIT(1); } else { CP_WAIT(0); }
        __syncthreads();
        if (kt + 2 < NKT) load_tile(kt + 2, (kt + 2) % NSTAGE);

        const uint32_t* as = sh + (kt % NSTAGE) * STAGE_U;
        const uint32_t* bs = as + A_U;

#pragma unroll
        for (int ks = 0; ks < 4; ks++) {
            const int k0 = ks * 8;
            uint32_t afr[4][4];
#pragma unroll
            for (int mf = 0; mf < 4; mf++) {
                const uint32_t* ap = as + (warp_m + mf * 16 + gid) * ASTR + k0 + tig;
                afr[mf][0] = ap[0];
                afr[mf][1] = ap[8 * ASTR];
                afr[mf][2] = ap[4];
                afr[mf][3] = ap[8 * ASTR + 4];
            }
            uint32_t bfr[4][2];
#pragma unroll
            for (int nf = 0; nf < 4; nf++) {
                const uint32_t* bp = bs + (k0 + tig) * BSTR + warp_n + nf * 8 + gid;
                bfr[nf][0] = bp[0];
                bfr[nf][1] = bp[4 * BSTR];
            }
#pragma unroll
            for (int mf = 0; mf < 4; mf++)
#pragma unroll
                for (int nf = 0; nf < 4; nf++)
                    mma_tf32(acc[mf][nf], afr[mf], bfr[nf]);
        }
    }

    // Epilogue
#pragma unroll
    for (int mf = 0; mf < 4; mf++) {
#pragma unroll
        for (int nf = 0; nf < 4; nf++) {
            int row0 = by * 128 + warp_m + mf * 16 + gid;
            int col  = bx * 128 + warp_n + nf * 8 + tig * 2;
            float b0 = 0.f, b1 = 0.f;
            if (bias) { b0 = __ldg(bias + col); b1 = __ldg(bias + col + 1); }
            float2 v0 = make_float2(acc[mf][nf][0] + b0, acc[mf][nf][1] + b1);
            float2 v1 = make_float2(acc[mf][nf][2] + b0, acc[mf][nf][3] + b1);
            *(float2*)(C + (size_t)row0 * N + col) = v0;
            *(float2*)(C + (size_t)(row0 + 8) * N + col) = v1;
        }
    }
}

// ---------------------------------------------------------------------------
// Tensor-core causal GQA flash attention (tf32 mma.sync), round-4 proven.
// Epilogue stores ctx tf32-rounded (feeds gemm3 with zero in-loop cvt).
// ---------------------------------------------------------------------------
#define AKPAD 132
#define AVPAD 136
#define APPAD 68
#define ATT_SMEM_UINTS (64 * AKPAD + 64 * AVPAD + 4 * 16 * APPAD)
#define ATT_SMEM_BYTES (ATT_SMEM_UINTS * 4)

__global__ __launch_bounds__(128, 2) void attn_mma(
    const float* __restrict__ q, const float* __restrict__ kv,
    float* __restrict__ ctx)
{
    const int h  = blockIdx.x;
    const int qt = blockIdx.y;
    const int g  = h >> 2;

    extern __shared__ uint32_t smu[];
    uint32_t* Ksh = smu;
    uint32_t* Vsh = Ksh + 64 * AKPAD;
    uint32_t* Psh = Vsh + 64 * AVPAD;

    const int tid  = threadIdx.x;
    const int wid  = tid >> 5;
    const int lane = tid & 31;
    const int gid  = lane >> 2;
    const int tig  = lane & 3;

    uint32_t* Pw = Psh + wid * 16 * APPAD;

    const int r0 = qt * 64 + wid * 16;
    const int rowg0 = r0 + gid;
    const int rowg1 = r0 + gid + 8;

    uint32_t qf[16][4];
    {
        const float* qb = q + (size_t)rowg0 * D_DIM + h * HDIM;
#pragma unroll
        for (int kf = 0; kf < 16; kf++) {
            int c = kf * 8 + tig;
            qf[kf][0] = f2tf32(qb[c]);
            qf[kf][1] = f2tf32(qb[8 * D_DIM + c]);
            qf[kf][2] = f2tf32(qb[c + 4]);
            qf[kf][3] = f2tf32(qb[8 * D_DIM + c + 4]);
        }
    }

    float o[16][4];
#pragma unroll
    for (int nf = 0; nf < 16; nf++)
#pragma unroll
        for (int j = 0; j < 4; j++) o[nf][j] = 0.f;
    float m0 = -1e30f, m1 = -1e30f, l0 = 0.f, l1 = 0.f;
    const float scale = 0.08838834764831845f;

    for (int kt = 0; kt <= qt; kt++) {
        __syncthreads();
        const float* kvb = kv + (size_t)(kt * 64) * KVDIM + g * (2 * HDIM);
        for (int i = tid; i < 64 * 32; i += 128) {
            int row = i >> 5;
            int c4  = (i & 31) * 4;
            float4 kk = *(const float4*)(kvb + (size_t)row * KVDIM + c4);
            float4 vv = *(const float4*)(kvb + (size_t)row * KVDIM + HDIM + c4);
            uint32_t* kp = Ksh + row * AKPAD + c4;
            kp[0] = f2tf32(kk.x); kp[1] = f2tf32(kk.y);
            kp[2] = f2tf32(kk.z); kp[3] = f2tf32(kk.w);
            uint32_t* vp = Vsh + row * AVPAD + c4;
            vp[0] = f2tf32(vv.x); vp[1] = f2tf32(vv.y);
            vp[2] = f2tf32(vv.z); vp[3] = f2tf32(vv.w);
        }
        __syncthreads();

        float sa[8][4];
#pragma unroll
        for (int nf = 0; nf < 8; nf++)
#pragma unroll
            for (int j = 0; j < 4; j++) sa[nf][j] = 0.f;

#pragma unroll
        for (int kf = 0; kf < 16; kf++) {
#pragma unroll
            for (int nf = 0; nf < 8; nf++) {
                const uint32_t* kp = Ksh + (nf * 8 + gid) * AKPAD + kf * 8 + tig;
                uint32_t bfr[2] = { kp[0], kp[4] };
                mma_tf32(sa[nf], qf[kf], bfr);
            }
        }

        const bool diag = (kt == qt);
#pragma unroll
        for (int nf = 0; nf < 8; nf++) {
            int c = kt * 64 + nf * 8 + 2 * tig;
#pragma unroll
            for (int j = 0; j < 4; j++) sa[nf][j] *= scale;
            if (diag) {
                if (c     > rowg0) sa[nf][0] = -1e30f;
                if (c + 1 > rowg0) sa[nf][1] = -1e30f;
                if (c     > rowg1) sa[nf][2] = -1e30f;
                if (c + 1 > rowg1) sa[nf][3] = -1e30f;
            }
        }

        float mx0 = -1e30f, mx1 = -1e30f;
#pragma unroll
        for (int nf = 0; nf < 8; nf++) {
            mx0 = fmaxf(mx0, fmaxf(sa[nf][0], sa[nf][1]));
            mx1 = fmaxf(mx1, fmaxf(sa[nf][2], sa[nf][3]));
        }
        mx0 = fmaxf(mx0, __shfl_xor_sync(0xffffffff, mx0, 1));
        mx0 = fmaxf(mx0, __shfl_xor_sync(0xffffffff, mx0, 2));
        mx1 = fmaxf(mx1, __shfl_xor_sync(0xffffffff, mx1, 1));
        mx1 = fmaxf(mx1, __shfl_xor_sync(0xffffffff, mx1, 2));

        float mn0 = fmaxf(m0, mx0), mn1 = fmaxf(m1, mx1);
        float al0 = __expf(m0 - mn0), al1 = __expf(m1 - mn1);

        float s0 = 0.f, s1 = 0.f;
#pragma unroll
        for (int nf = 0; nf < 8; nf++) {
            float p00 = __expf(sa[nf][0] - mn0);
            float p01 = __expf(sa[nf][1] - mn0);
            float p10 = __expf(sa[nf][2] - mn1);
            float p11 = __expf(sa[nf][3] - mn1);
            s0 += p00 + p01;
            s1 += p10 + p11;
            uint32_t* pp0 = Pw + gid * APPAD + nf * 8 + 2 * tig;
            pp0[0] = f2tf32(p00); pp0[1] = f2tf32(p01);
            uint32_t* pp1 = Pw + (gid + 8) * APPAD + nf * 8 + 2 * tig;
            pp1[0] = f2tf32(p10); pp1[1] = f2tf32(p11);
        }
        s0 += __shfl_xor_sync(0xffffffff, s0, 1);
        s0 += __shfl_xor_sync(0xffffffff, s0, 2);
        s1 += __shfl_xor_sync(0xffffffff, s1, 1);
        s1 += __shfl_xor_sync(0xffffffff, s1, 2);

        l0 = l0 * al0 + s0;
        l1 = l1 * al1 + s1;
        m0 = mn0; m1 = mn1;

#pragma unroll
        for (int nf = 0; nf < 16; nf++) {
            o[nf][0] *= al0; o[nf][1] *= al0;
            o[nf][2] *= al1; o[nf][3] *= al1;
        }
        __syncwarp();

#pragma unroll
        for (int kf = 0; kf < 8; kf++) {
            uint32_t pa[4];
            pa[0] = Pw[gid * APPAD + kf * 8 + tig];
            pa[1] = Pw[(gid + 8) * APPAD + kf * 8 + tig];
            pa[2] = Pw[gid * APPAD + kf * 8 + tig + 4];
            pa[3] = Pw[(gid + 8) * APPAD + kf * 8 + tig + 4];
#pragma unroll
            for (int nf = 0; nf < 16; nf++) {
                const uint32_t* vp = Vsh + (kf * 8 + tig) * AVPAD + nf * 8 + gid;
                uint32_t bfr[2] = { vp[0], vp[4 * AVPAD] };
                mma_tf32(o[nf], pa, bfr);
            }
        }
        __syncwarp();
    }

    float inv0 = 1.0f / l0, inv1 = 1.0f / l1;
    float* cb = ctx + (size_t)rowg0 * D_DIM + h * HDIM;
#pragma unroll
    for (int nf = 0; nf < 16; nf++) {
        int c = nf * 8 + 2 * tig;
        float2 w0 = make_float2(
            __uint_as_float(f2tf32(o[nf][0] * inv0)),
            __uint_as_float(f2tf32(o[nf][1] * inv0)));
        float2 w1 = make_float2(
            __uint_as_float(f2tf32(o[nf][2] * inv1)),
            __uint_as_float(f2tf32(o[nf][3] * inv1)));
        *(float2*)(cb + c) = w0;
        *(float2*)(cb + 8 * D_DIM + c) = w1;
    }
}

// ---------------------------------------------------------------------------
// Launch
// ---------------------------------------------------------------------------
extern "C" void kernel_launch(void* const* d_in, const int* in_sizes, int n_in,
                              void* d_out, int out_size)
{
    const float* x   = (const float*)d_in[0];
    const float* Wq  = (const float*)d_in[1];
    const float* Wkv = (const float*)d_in[2];
    const float* Wo  = (const float*)d_in[3];
    const float* bo  = (const float*)d_in[4];
    float* out = (float*)d_out;

    float *qp, *kvp, *ctxp;
    uint32_t *xtf, *wq32, *wkv32, *wo32;
    cudaGetSymbolAddress((void**)&qp,    g_q);
    cudaGetSymbolAddress((void**)&kvp,   g_kv);
    cudaGetSymbolAddress((void**)&ctxp,  g_ctx);
    cudaGetSymbolAddress((void**)&xtf,   g_xtf);
    cudaGetSymbolAddress((void**)&wq32,  g_wq32);
    cudaGetSymbolAddress((void**)&wkv32, g_wkv32);
    cudaGetSymbolAddress((void**)&wo32,  g_wo32);

    cudaFuncSetAttribute(attn_mma,
                         cudaFuncAttributeMaxDynamicSharedMemorySize,
                         ATT_SMEM_BYTES);
    cudaFuncSetAttribute(gemm_mma,
                         cudaFuncAttributeMaxDynamicSharedMemorySize,
                         GSMEM_BYTES);

    // Prepass: elementwise tf32 conversion (no layout change)
    cvt_tf32<<<(T_LEN * D_DIM / 4 + 255) / 256, 256>>>(
        (const float4*)x, (uint4*)xtf, T_LEN * D_DIM / 4);
    cvt_tf32<<<(D_DIM * D_DIM / 4 + 255) / 256, 256>>>(
        (const float4*)Wq, (uint4*)wq32, D_DIM * D_DIM / 4);
    cvt_tf32<<<(D_DIM * KVDIM / 4 + 255) / 256, 256>>>(
        (const float4*)Wkv, (uint4*)wkv32, D_DIM * KVDIM / 4);
    cvt_tf32<<<(D_DIM * D_DIM / 4 + 255) / 256, 256>>>(
        (const float4*)Wo, (uint4*)wo32, D_DIM * D_DIM / 4);

    // 1) q = x @ Wq
    gemm_mma<<<dim3(D_DIM / 128, T_LEN / 128), 256, GSMEM_BYTES>>>(
        xtf, wq32, qp, nullptr, D_DIM);
    // 2) kv = x @ Wkv
    gemm_mma<<<dim3(KVDIM / 128, T_LEN / 128), 256, GSMEM_BYTES>>>(
        xtf, wkv32, kvp, nullptr, KVDIM);
    // 3) attention (writes ctx tf32-rounded)
    attn_mma<<<dim3(NHEAD, T_LEN / 64), 128, ATT_SMEM_BYTES>>>(qp, kvp, ctxp);
    // 4) out = ctx @ Wo + bo
    gemm_mma<<<dim3(D_DIM / 128, T_LEN / 128), 256, GSMEM_BYTES>>>(
        (const uint32_t*)ctxp, wo32, out, bo, D_DIM);

    (void)in_sizes; (void)n_in; (void)out_size;
}

// round 9
// speedup vs baseline: 1.1478x; 1.1478x over previous
#include <cuda_runtime.h>
#include <cuda_bf16.h>
#include <cstdint>
#include <math.h>

// Problem constants
#define T_LEN 2048
#define D_DIM 4096
#define NHEAD 32
#define NGRP 8
#define HDIM 128
#define KVDIM 2048   // 2 * HDIM * NGRP

// Scratch (no cudaMalloc allowed)
__device__ float g_q[T_LEN * D_DIM];     // 32 MB
__device__ float g_kv[T_LEN * KVDIM];    // 16 MB
__device__ float g_ctx[T_LEN * D_DIM];   // 32 MB

// ---------------------------------------------------------------------------
// Helpers
// ---------------------------------------------------------------------------
__device__ __forceinline__ uint32_t smem_u32(const void* p) {
    uint32_t a;
    asm("{ .reg .u64 t; cvta.to.shared.u64 t, %1; cvt.u32.u64 %0, t; }"
        : "=r"(a) : "l"(p));
    return a;
}
#define CP_ASYNC16(smem, gptr) \
    asm volatile("cp.async.cg.shared.global [%0], [%1], 16;" \
                 :: "r"(smem), "l"(gptr) : "memory")
#define CP_COMMIT() asm volatile("cp.async.commit_group;" ::: "memory")
#define CP_WAIT(N)  asm volatile("cp.async.wait_group %0;" :: "n"(N) : "memory")

__device__ __forceinline__ uint32_t f2tf32(float f) {
    uint32_t u;
    asm("cvt.rna.tf32.f32 %0, %1;" : "=r"(u) : "f"(f));
    return u;
}
__device__ __forceinline__ void mma_tf32(float* c, const uint32_t* a,
                                         const uint32_t* b) {
    asm volatile(
        "mma.sync.aligned.m16n8k8.row.col.f32.tf32.tf32.f32 "
        "{%0,%1,%2,%3}, {%4,%5,%6,%7}, {%8,%9}, {%0,%1,%2,%3};"
        : "+f"(c[0]), "+f"(c[1]), "+f"(c[2]), "+f"(c[3])
        : "r"(a[0]), "r"(a[1]), "r"(a[2]), "r"(a[3]), "r"(b[0]), "r"(b[1]));
}

// ---------------------------------------------------------------------------
// tf32 mma.sync GEMM, BK=16, 3-stage cp.async ring, ONE barrier per tile.
// Dual-output fusion: N-tile blocks [0,NX0) use {B0,C0,N0,bias0},
// the rest use {B1,C1,N1,no bias}.
// BM=128, BN=128, 256 threads (8 warps 2x4), warp tile 64x32.
// Stage smem: A 128x20 f32 + B 16x136 f32 = 18944 B; 3 stages = 56832 B.
// ---------------------------------------------------------------------------
#define GK 4096
#define NT (GK / 16)
#define AS_STRIDE 20
#define BS_STRIDE 136
#define AS_FLOATS (128 * AS_STRIDE)   // 2560
#define BS_FLOATS (16 * BS_STRIDE)    // 2176
#define STAGE_F (AS_FLOATS + BS_FLOATS)  // 4736 floats
#define NSTAGE 3
#define GSMEM_BYTES (NSTAGE * STAGE_F * 4)  // 56832

__global__ __launch_bounds__(256, 2) void gemm_mma(
    const float* __restrict__ A,
    const float* __restrict__ B0, float* __restrict__ C0,
    const float* __restrict__ bias0, int N0, int NX0,
    const float* __restrict__ B1, float* __restrict__ C1, int N1)
{
    extern __shared__ float sh[];
    const uint32_t smb = smem_u32(sh);

    const int tid = threadIdx.x;
    const int wid = tid >> 5;
    const int lane = tid & 31;
    const int gid = lane >> 2;
    const int tig = lane & 3;
    const int warp_m = (wid & 1) * 64;
    const int warp_n = (wid >> 1) * 32;

    const int by = blockIdx.y;
    int bx = blockIdx.x;

    const float* B; float* C; const float* bias; int N;
    if (bx < NX0) { B = B0; C = C0; bias = bias0; N = N0; }
    else          { B = B1; C = C1; bias = nullptr; N = N1; bx -= NX0; }

    const float* Ab = A + (size_t)by * 128 * GK;
    const float* Bb = B + (size_t)bx * 128;

    // Loader slots (R4-proven): A 512 chunks, B 512 chunks, 2+2 per thread
    const int a_r0 = tid >> 2,         a_c0 = tid & 3;
    const int a_r1 = (tid + 256) >> 2, a_c1 = (tid + 256) & 3;
    const int b_r0 = tid >> 5,         b_c0 = tid & 31;
    const int b_r1 = (tid + 256) >> 5, b_c1 = (tid + 256) & 31;

    auto load_tile = [&](int kt, int s) {
        const float* ag = Ab + kt * 16;
        const float* bg = Bb + (size_t)(kt * 16) * N;
        uint32_t ab = smb + 4 * (s * STAGE_F);
        uint32_t bb = ab + 4 * AS_FLOATS;
        CP_ASYNC16(ab + (a_r0 * AS_STRIDE + a_c0 * 4) * 4,
                   ag + (size_t)a_r0 * GK + a_c0 * 4);
        CP_ASYNC16(ab + (a_r1 * AS_STRIDE + a_c1 * 4) * 4,
                   ag + (size_t)a_r1 * GK + a_c1 * 4);
        CP_ASYNC16(bb + (b_r0 * BS_STRIDE + b_c0 * 4) * 4,
                   bg + (size_t)b_r0 * N + b_c0 * 4);
        CP_ASYNC16(bb + (b_r1 * BS_STRIDE + b_c1 * 4) * 4,
                   bg + (size_t)b_r1 * N + b_c1 * 4);
        CP_COMMIT();
    };

    float acc[4][4][4];
#pragma unroll
    for (int i = 0; i < 4; i++)
#pragma unroll
        for (int j = 0; j < 4; j++)
#pragma unroll
            for (int k = 0; k < 4; k++) acc[i][j][k] = 0.f;

    load_tile(0, 0);
    load_tile(1, 1);

    for (int kt = 0; kt < NT; kt++) {
        if (kt < NT - 1) { CP_WAIT(1); } else { CP_WAIT(0); }
        __syncthreads();
        if (kt + 2 < NT) load_tile(kt + 2, (kt + 2) % NSTAGE);

        const float* as = sh + (kt % NSTAGE) * STAGE_F;
        const float* bs = as + AS_FLOATS;

#pragma unroll
        for (int ks = 0; ks < 2; ks++) {
            const int k0 = ks * 8;
            uint32_t afr[4][4];
#pragma unroll
            for (int mf = 0; mf < 4; mf++) {
                const float* ap = as + (warp_m + mf * 16 + gid) * AS_STRIDE + k0 + tig;
                afr[mf][0] = f2tf32(ap[0]);
                afr[mf][1] = f2tf32(ap[8 * AS_STRIDE]);
                afr[mf][2] = f2tf32(ap[4]);
                afr[mf][3] = f2tf32(ap[8 * AS_STRIDE + 4]);
            }
            uint32_t bfr[4][2];
#pragma unroll
            for (int nf = 0; nf < 4; nf++) {
                const float* bp = bs + (k0 + tig) * BS_STRIDE + warp_n + nf * 8 + gid;
                bfr[nf][0] = f2tf32(bp[0]);
                bfr[nf][1] = f2tf32(bp[4 * BS_STRIDE]);
            }
#pragma unroll
            for (int mf = 0; mf < 4; mf++)
#pragma unroll
                for (int nf = 0; nf < 4; nf++)
                    mma_tf32(acc[mf][nf], afr[mf], bfr[nf]);
        }
    }

    // Epilogue
#pragma unroll
    for (int mf = 0; mf < 4; mf++) {
#pragma unroll
        for (int nf = 0; nf < 4; nf++) {
            int row0 = by * 128 + warp_m + mf * 16 + gid;
            int col  = bx * 128 + warp_n + nf * 8 + tig * 2;
            float b0 = 0.f, b1 = 0.f;
            if (bias) { b0 = __ldg(bias + col); b1 = __ldg(bias + col + 1); }
            float2 v0 = make_float2(acc[mf][nf][0] + b0, acc[mf][nf][1] + b1);
            float2 v1 = make_float2(acc[mf][nf][2] + b0, acc[mf][nf][3] + b1);
            *(float2*)(C + (size_t)row0 * N + col) = v0;
            *(float2*)(C + (size_t)(row0 + 8) * N + col) = v1;
        }
    }
}

// ---------------------------------------------------------------------------
// Tensor-core causal GQA flash attention (tf32 mma.sync), round-4 proven.
// ---------------------------------------------------------------------------
#define AKPAD 132
#define AVPAD 136
#define APPAD 68
#define ATT_SMEM_UINTS (64 * AKPAD + 64 * AVPAD + 4 * 16 * APPAD)
#define ATT_SMEM_BYTES (ATT_SMEM_UINTS * 4)

__global__ __launch_bounds__(128, 2) void attn_mma(
    const float* __restrict__ q, const float* __restrict__ kv,
    float* __restrict__ ctx)
{
    const int h  = blockIdx.x;
    const int qt = blockIdx.y;
    const int g  = h >> 2;

    extern __shared__ uint32_t smu[];
    uint32_t* Ksh = smu;
    uint32_t* Vsh = Ksh + 64 * AKPAD;
    uint32_t* Psh = Vsh + 64 * AVPAD;

    const int tid  = threadIdx.x;
    const int wid  = tid >> 5;
    const int lane = tid & 31;
    const int gid  = lane >> 2;
    const int tig  = lane & 3;

    uint32_t* Pw = Psh + wid * 16 * APPAD;

    const int r0 = qt * 64 + wid * 16;
    const int rowg0 = r0 + gid;
    const int rowg1 = r0 + gid + 8;

    uint32_t qf[16][4];
    {
        const float* qb = q + (size_t)rowg0 * D_DIM + h * HDIM;
#pragma unroll
        for (int kf = 0; kf < 16; kf++) {
            int c = kf * 8 + tig;
            qf[kf][0] = f2tf32(qb[c]);
            qf[kf][1] = f2tf32(qb[8 * D_DIM + c]);
            qf[kf][2] = f2tf32(qb[c + 4]);
            qf[kf][3] = f2tf32(qb[8 * D_DIM + c + 4]);
        }
    }

    float o[16][4];
#pragma unroll
    for (int nf = 0; nf < 16; nf++)
#pragma unroll
        for (int j = 0; j < 4; j++) o[nf][j] = 0.f;
    float m0 = -1e30f, m1 = -1e30f, l0 = 0.f, l1 = 0.f;
    const float scale = 0.08838834764831845f;

    for (int kt = 0; kt <= qt; kt++) {
        __syncthreads();
        const float* kvb = kv + (size_t)(kt * 64) * KVDIM + g * (2 * HDIM);
        for (int i = tid; i < 64 * 32; i += 128) {
            int row = i >> 5;
            int c4  = (i & 31) * 4;
            float4 kk = *(const float4*)(kvb + (size_t)row * KVDIM + c4);
            float4 vv = *(const float4*)(kvb + (size_t)row * KVDIM + HDIM + c4);
            uint32_t* kp = Ksh + row * AKPAD + c4;
            kp[0] = f2tf32(kk.x); kp[1] = f2tf32(kk.y);
            kp[2] = f2tf32(kk.z); kp[3] = f2tf32(kk.w);
            uint32_t* vp = Vsh + row * AVPAD + c4;
            vp[0] = f2tf32(vv.x); vp[1] = f2tf32(vv.y);
            vp[2] = f2tf32(vv.z); vp[3] = f2tf32(vv.w);
        }
        __syncthreads();

        float sa[8][4];
#pragma unroll
        for (int nf = 0; nf < 8; nf++)
#pragma unroll
            for (int j = 0; j < 4; j++) sa[nf][j] = 0.f;

#pragma unroll
        for (int kf = 0; kf < 16; kf++) {
#pragma unroll
            for (int nf = 0; nf < 8; nf++) {
                const uint32_t* kp = Ksh + (nf * 8 + gid) * AKPAD + kf * 8 + tig;
                uint32_t bfr[2] = { kp[0], kp[4] };
                mma_tf32(sa[nf], qf[kf], bfr);
            }
        }

        const bool diag = (kt == qt);
#pragma unroll
        for (int nf = 0; nf < 8; nf++) {
            int c = kt * 64 + nf * 8 + 2 * tig;
#pragma unroll
            for (int j = 0; j < 4; j++) sa[nf][j] *= scale;
            if (diag) {
                if (c     > rowg0) sa[nf][0] = -1e30f;
                if (c + 1 > rowg0) sa[nf][1] = -1e30f;
                if (c     > rowg1) sa[nf][2] = -1e30f;
                if (c + 1 > rowg1) sa[nf][3] = -1e30f;
            }
        }

        float mx0 = -1e30f, mx1 = -1e30f;
#pragma unroll
        for (int nf = 0; nf < 8; nf++) {
            mx0 = fmaxf(mx0, fmaxf(sa[nf][0], sa[nf][1]));
            mx1 = fmaxf(mx1, fmaxf(sa[nf][2], sa[nf][3]));
        }
        mx0 = fmaxf(mx0, __shfl_xor_sync(0xffffffff, mx0, 1));
        mx0 = fmaxf(mx0, __shfl_xor_sync(0xffffffff, mx0, 2));
        mx1 = fmaxf(mx1, __shfl_xor_sync(0xffffffff, mx1, 1));
        mx1 = fmaxf(mx1, __shfl_xor_sync(0xffffffff, mx1, 2));

        float mn0 = fmaxf(m0, mx0), mn1 = fmaxf(m1, mx1);
        float al0 = __expf(m0 - mn0), al1 = __expf(m1 - mn1);

        float s0 = 0.f, s1 = 0.f;
#pragma unroll
        for (int nf = 0; nf < 8; nf++) {
            float p00 = __expf(sa[nf][0] - mn0);
            float p01 = __expf(sa[nf][1] - mn0);
            float p10 = __expf(sa[nf][2] - mn1);
            float p11 = __expf(sa[nf][3] - mn1);
            s0 += p00 + p01;
            s1 += p10 + p11;
            uint32_t* pp0 = Pw + gid * APPAD + nf * 8 + 2 * tig;
            pp0[0] = f2tf32(p00); pp0[1] = f2tf32(p01);
            uint32_t* pp1 = Pw + (gid + 8) * APPAD + nf * 8 + 2 * tig;
            pp1[0] = f2tf32(p10); pp1[1] = f2tf32(p11);
        }
        s0 += __shfl_xor_sync(0xffffffff, s0, 1);
        s0 += __shfl_xor_sync(0xffffffff, s0, 2);
        s1 += __shfl_xor_sync(0xffffffff, s1, 1);
        s1 += __shfl_xor_sync(0xffffffff, s1, 2);

        l0 = l0 * al0 + s0;
        l1 = l1 * al1 + s1;
        m0 = mn0; m1 = mn1;

#pragma unroll
        for (int nf = 0; nf < 16; nf++) {
            o[nf][0] *= al0; o[nf][1] *= al0;
            o[nf][2] *= al1; o[nf][3] *= al1;
        }
        __syncwarp();

#pragma unroll
        for (int kf = 0; kf < 8; kf++) {
            uint32_t pa[4];
            pa[0] = Pw[gid * APPAD + kf * 8 + tig];
            pa[1] = Pw[(gid + 8) * APPAD + kf * 8 + tig];
            pa[2] = Pw[gid * APPAD + kf * 8 + tig + 4];
            pa[3] = Pw[(gid + 8) * APPAD + kf * 8 + tig + 4];
#pragma unroll
            for (int nf = 0; nf < 16; nf++) {
                const uint32_t* vp = Vsh + (kf * 8 + tig) * AVPAD + nf * 8 + gid;
                uint32_t bfr[2] = { vp[0], vp[4 * AVPAD] };
                mma_tf32(o[nf], pa, bfr);
            }
        }
        __syncwarp();
    }

    float inv0 = 1.0f / l0, inv1 = 1.0f / l1;
    float* cb = ctx + (size_t)rowg0 * D_DIM + h * HDIM;
#pragma unroll
    for (int nf = 0; nf < 16; nf++) {
        int c = nf * 8 + 2 * tig;
        *(float2*)(cb + c) = make_float2(o[nf][0] * inv0, o[nf][1] * inv0);
        *(float2*)(cb + 8 * D_DIM + c) = make_float2(o[nf][2] * inv1, o[nf][3] * inv1);
    }
}

// ---------------------------------------------------------------------------
// Launch
// ---------------------------------------------------------------------------
extern "C" void kernel_launch(void* const* d_in, const int* in_sizes, int n_in,
                              void* d_out, int out_size)
{
    const float* x   = (const float*)d_in[0];
    const float* Wq  = (const float*)d_in[1];
    const float* Wkv = (const float*)d_in[2];
    const float* Wo  = (const float*)d_in[3];
    const float* bo  = (const float*)d_in[4];
    float* out = (float*)d_out;

    float *qp, *kvp, *ctxp;
    cudaGetSymbolAddress((void**)&qp,   g_q);
    cudaGetSymbolAddress((void**)&kvp,  g_kv);
    cudaGetSymbolAddress((void**)&ctxp, g_ctx);

    cudaFuncSetAttribute(attn_mma,
                         cudaFuncAttributeMaxDynamicSharedMemorySize,
                         ATT_SMEM_BYTES);
    cudaFuncSetAttribute(gemm_mma,
                         cudaFuncAttributeMaxDynamicSharedMemorySize,
                         GSMEM_BYTES);

    // 1+2) fused: q = x@Wq (bx<32), kv = x@Wkv (bx>=32)
    gemm_mma<<<dim3(D_DIM / 128 + KVDIM / 128, T_LEN / 128), 256, GSMEM_BYTES>>>(
        x, Wq, qp, nullptr, D_DIM, D_DIM / 128, Wkv, kvp, KVDIM);
    // 3) attention
    attn_mma<<<dim3(NHEAD, T_LEN / 64), 128, ATT_SMEM_BYTES>>>(qp, kvp, ctxp);
    // 4) out = ctx @ Wo + bo
    gemm_mma<<<dim3(D_DIM / 128, T_LEN / 128), 256, GSMEM_BYTES>>>(
        ctxp, Wo, out, bo, D_DIM, D_DIM / 128, Wo, out, D_DIM);

    (void)in_sizes; (void)n_in; (void)out_size;
}